// round 6
// baseline (speedup 1.0000x reference)
#include <cuda_runtime.h>
#include <cstdint>

// ---------------- problem constants ----------------
#define NB 8
#define MO 12
#define DD 512
#define NO 37
#define NA 6
#define NT 3
#define EMB 128
#define NAA 100
#define NC 300
#define KK 72            // MO*NA
#define NP 5112          // KK*(KK-1)
#define FD 1536

// output layout (flattened tuple, all f32)
#define OFF_FINAL 0
#define OFF_PL    2400                       // pair_logits [8,5112,3]
#define OFF_TT    (2400 + 122688)            // tr_targets  [8,5112,3]
#define OFF_ACT   (2400 + 122688 + 122688)   // act_out [8,12,6]
#define OFF_OBJ   (OFF_ACT + 576)            // obj_out [8,12,37]

// ---------------- scratch (__device__ globals; no allocs) ----------------
__device__ float    g_pooled[NB * DD];
__device__ float    g_nonexist[NB * NC];
__device__ unsigned g_seg[NB * NC];
__device__ float    g_inpdot[NB * MO * 6];   // [b][o][t*2+half]
__device__ float    g_oembdot[NO * 6];       // [o][t*2+half]
__device__ float    g_aembdot[NA * 6];       // [a][t*2+half]
__device__ float    g_invconst[NT];          // b_tr[t] - sum(W_tr[t,:])

// monotone float<->uint encode for atomicMax on floats
__device__ __forceinline__ unsigned encf(float f) {
    unsigned u = __float_as_uint(f);
    return (u & 0x80000000u) ? ~u : (u | 0x80000000u);
}
__device__ __forceinline__ float decf(unsigned u) {
    return (u & 0x80000000u) ? __uint_as_float(u & 0x7fffffffu)
                             : __uint_as_float(~u);
}

// ---------------- K0: pooled mean + clear seg scratch ----------------
__global__ void k_pool(const float* __restrict__ inp, const float* __restrict__ objmask) {
    int b = blockIdx.x, d = threadIdx.x;
    float sm = 0.f, acc = 0.f;
#pragma unroll
    for (int o = 0; o < MO; o++) {
        float m = objmask[b * MO + o];
        sm += m;
        acc += inp[(b * MO + o) * DD + d] * m;
    }
    g_pooled[b * DD + d] = acc / sm;
    if (d < NC) g_seg[b * NC + d] = 0u;
}

// ---------------- K1: warp-per-dot for all the GEMV-ish work ----------------
__device__ __forceinline__ float warpdot(const float* __restrict__ a,
                                         const float* __restrict__ w, int n, int lane) {
    float s = 0.f;
    for (int d = lane; d < n; d += 32) s += a[d] * w[d];
#pragma unroll
    for (int o = 16; o; o >>= 1) s += __shfl_down_sync(0xffffffffu, s, o);
    return s;  // valid on lane 0
}

// task ranges
#define T_OBJ  3552               // 96*37
#define T_ACT  (T_OBJ + 576)      // 96*6
#define T_NE   (T_ACT + 2400)     // 8*300
#define T_IND  (T_NE + 576)       // 96*6  inp partial dots vs W_tr
#define T_OE   (T_IND + 222)      // 37*6
#define T_AE   (T_OE + 36)        // 6*6
#define T_INV  (T_AE + 3)
#define NWARPS T_INV              // 7365

__global__ void k_dots(const float* __restrict__ inp,
                       const float* __restrict__ Wobj, const float* __restrict__ bobj,
                       const float* __restrict__ Wact, const float* __restrict__ bact,
                       const float* __restrict__ Wtr,  const float* __restrict__ btr,
                       const float* __restrict__ Wne,  const float* __restrict__ bne,
                       const float* __restrict__ oemb, const float* __restrict__ aemb,
                       float* __restrict__ out) {
    int warp = (blockIdx.x * blockDim.x + threadIdx.x) >> 5;
    int lane = threadIdx.x & 31;
    if (warp >= NWARPS) return;

    if (warp < T_OBJ) {
        int c = warp % NO, bo = warp / NO;
        float r = warpdot(inp + bo * DD, Wobj + c * DD, DD, lane);
        if (lane == 0) out[OFF_OBJ + bo * NO + c] = r + bobj[c];
    } else if (warp < T_ACT) {
        int t = warp - T_OBJ;
        int c = t % NA, bo = t / NA;
        float r = warpdot(inp + bo * DD, Wact + c * DD, DD, lane);
        if (lane == 0) out[OFF_ACT + bo * NA + c] = r + bact[c];
    } else if (warp < T_NE) {
        int t = warp - T_ACT;
        int c = t % NC, b = t / NC;
        float r = warpdot(g_pooled + b * DD, Wne + c * DD, DD, lane);
        if (lane == 0) g_nonexist[b * NC + c] = r + bne[c];
    } else if (warp < T_IND) {
        int t = warp - T_NE;
        int idx = t % 6, bo = t / 6;
        int tt = idx >> 1, half = idx & 1;
        float r = warpdot(inp + bo * DD, Wtr + tt * FD + half * 768, DD, lane);
        if (lane == 0) g_inpdot[bo * 6 + idx] = r;
    } else if (warp < T_OE) {
        int t = warp - T_IND;
        int idx = t % 6, o = t / 6;
        int tt = idx >> 1, half = idx & 1;
        float r = warpdot(oemb + o * EMB, Wtr + tt * FD + half * 768 + DD, EMB, lane);
        if (lane == 0) g_oembdot[o * 6 + idx] = r;
    } else if (warp < T_AE) {
        int t = warp - T_OE;
        int idx = t % 6, a = t / 6;
        int tt = idx >> 1, half = idx & 1;
        float r = warpdot(aemb + a * EMB, Wtr + tt * FD + half * 768 + DD + EMB, EMB, lane);
        if (lane == 0) g_aembdot[a * 6 + idx] = r;
    } else {
        int tt = warp - T_AE;
        float s = 0.f;
        for (int d = lane; d < FD; d += 32) s -= Wtr[tt * FD + d];
#pragma unroll
        for (int o = 16; o; o >>= 1) s += __shfl_down_sync(0xffffffffu, s, o);
        if (lane == 0) g_invconst[tt] = s + btr[tt];
    }
}

// ---------------- K2: pair kernel ----------------
__global__ void k_pairs(const float* __restrict__ out_ro,
                        const float* __restrict__ objmask,
                        const int* __restrict__ AA,
                        const float* __restrict__ TR,
                        const int* __restrict__ lookup,
                        const float* __restrict__ btr,
                        float* __restrict__ out) {
    int b = blockIdx.x;
    int tid = threadIdx.x;

    __shared__ float s_dA[KK][NT], s_dB[KK][NT];
    __shared__ int s_aa[KK];
    __shared__ unsigned s_bits[3];
    __shared__ int s_am[MO];
    __shared__ float s_btr[NT], s_inv[NT];

    if (tid < MO) {
        const float* row = out_ro + OFF_OBJ + (b * MO + tid) * NO;
        float best = row[0]; int bi = 0;
#pragma unroll
        for (int c = 1; c < NO; c++) { float v = row[c]; if (v > best) { best = v; bi = c; } }
        s_am[tid] = bi;
    }
    if (tid < NT) { s_btr[tid] = btr[tid]; s_inv[tid] = g_invconst[tid]; }
    __syncthreads();

    bool sel = false;
    if (tid < KK) {
        int o = tid / NA, a = tid % NA;
        float act = out_ro[OFF_ACT + b * KK + tid];
        float m = objmask[b * MO + o];
        float pa = (act > 0.f) ? m : 0.f;
        int aa = AA[b * KK + tid];
        sel = (pa == 1.0f) && (aa != -1);
        s_aa[tid] = aa;
        int po = s_am[o];
#pragma unroll
        for (int t = 0; t < NT; t++) {
            s_dA[tid][t] = g_inpdot[(b * MO + o) * 6 + t * 2 + 0]
                         + g_oembdot[po * 6 + t * 2 + 0]
                         + g_aembdot[a * 6 + t * 2 + 0];
            s_dB[tid][t] = g_inpdot[(b * MO + o) * 6 + t * 2 + 1]
                         + g_oembdot[po * 6 + t * 2 + 1]
                         + g_aembdot[a * 6 + t * 2 + 1];
        }
    }
    if (tid < 96) {
        unsigned bal = __ballot_sync(0xffffffffu, sel);
        if ((tid & 31) == 0) s_bits[tid >> 5] = bal;
    }
    __syncthreads();

    unsigned w0 = s_bits[0], w1 = s_bits[1], w2 = s_bits[2];
    int S = __popc(w0) + __popc(w1) + __popc(w2);
    int Nv = S * (S - 1);

    int p = blockIdx.y * blockDim.x + tid;
    if (p >= NP) return;

    int i = p / (KK - 1);
    int jr = p - i * (KK - 1);
    int j = jr + (jr >= i ? 1 : 0);

    auto lowmask = [](int r) -> unsigned {
        return (r >= 32) ? 0xffffffffu : ((r <= 0) ? 0u : ((1u << r) - 1u));
    };
    auto getbit = [&](int k) -> int {
        unsigned w = (k < 32) ? w0 : ((k < 64) ? w1 : w2);
        return (w >> (k & 31)) & 1;
    };
    auto pfx = [&](int k) -> int {
        return __popc(w0 & lowmask(k)) + __popc(w1 & lowmask(k - 32)) + __popc(w2 & lowmask(k - 64));
    };

    int vi = getbit(i), vj = getbit(j);
    int vb = pfx(i) * (S - 1) + (vi ? (pfx(j) - (j > i ? 1 : 0)) : 0);
    bool valid = vi && vj;
    int pos = valid ? vb : (Nv + p - vb);

    float* pl = out + OFF_PL + (size_t)(b * NP + pos) * NT;
    float* tt = out + OFF_TT + (size_t)(b * NP + pos) * NT;

    if (valid) {
        int aai = s_aa[i], aaj = s_aa[j];
        const float* tr = TR + ((size_t)(b * KK + i) * KK + j) * NT;
        const int* lk = lookup + (aai * NAA + aaj) * NT;
#pragma unroll
        for (int t = 0; t < NT; t++) {
            float lg = s_dA[i][t] + s_dB[j][t] + s_btr[t];
            pl[t] = lg;
            tt[t] = tr[t];
            atomicMax(&g_seg[b * NC + lk[t]], encf(lg));
        }
    } else {
#pragma unroll
        for (int t = 0; t < NT; t++) { pl[t] = s_inv[t]; tt[t] = -1.0f; }
    }
}

// ---------------- K3: final select ----------------
__global__ void k_final(float* __restrict__ out) {
    int t = blockIdx.x * blockDim.x + threadIdx.x;
    if (t >= NB * NC) return;
    unsigned u = g_seg[t];
    out[OFF_FINAL + t] = u ? decf(u) : g_nonexist[t];
}

extern "C" void kernel_launch(void* const* d_in, const int* in_sizes, int n_in,
                              void* d_out, int out_size) {
    const float* inp     = (const float*)d_in[0];
    const float* objmask = (const float*)d_in[1];
    const float* TR      = (const float*)d_in[2];
    const float* Wobj    = (const float*)d_in[3];
    const float* bobj    = (const float*)d_in[4];
    const float* Wact    = (const float*)d_in[5];
    const float* bact    = (const float*)d_in[6];
    const float* Wtr     = (const float*)d_in[7];
    const float* btr     = (const float*)d_in[8];
    const float* Wne     = (const float*)d_in[9];
    const float* bne     = (const float*)d_in[10];
    const float* oemb    = (const float*)d_in[11];
    const float* aemb    = (const float*)d_in[12];
    const int*   AA      = (const int*)d_in[13];
    // d_in[14] = obj_act_lookup (eval-only branch, unused)
    const int*   lookup  = (const int*)d_in[15];
    float* out = (float*)d_out;

    k_pool<<<NB, DD>>>(inp, objmask);
    k_dots<<<(NWARPS * 32 + 255) / 256, 256>>>(inp, Wobj, bobj, Wact, bact,
                                               Wtr, btr, Wne, bne, oemb, aemb, out);
    k_pairs<<<dim3(NB, (NP + 255) / 256), 256>>>(out, objmask, AA, TR, lookup, btr, out);
    k_final<<<(NB * NC + 255) / 256, 256>>>(out);
}

// round 8
// speedup vs baseline: 1.2916x; 1.2916x over previous
#include <cuda_runtime.h>
#include <cstdint>

// ---------------- problem constants ----------------
#define NB 8
#define MO 12
#define DD 512
#define NO 37
#define NA 6
#define NT 3
#define EMB 128
#define NAA 100
#define NC 300
#define KK 72            // MO*NA
#define NP 5112          // KK*(KK-1)
#define FD 1536

// output layout (flattened tuple, all f32)
#define OFF_FINAL 0
#define OFF_PL    2400                       // pair_logits [8,5112,3]
#define OFF_TT    (2400 + 122688)            // tr_targets  [8,5112,3]
#define OFF_ACT   (2400 + 122688 + 122688)   // act_out [8,12,6]
#define OFF_OBJ   (OFF_ACT + 576)            // obj_out [8,12,37]

// ---------------- scratch (__device__ globals; no allocs) ----------------
__device__ float    g_nonexist[NB * NC];
__device__ unsigned g_seg[NB * NC];
__device__ float    g_inpdot[NB * MO * 6];   // [b][o][t*2+half]
__device__ float    g_oembdot[NO * 6];       // [o][t*2+half]
__device__ float    g_aembdot[NA * 6];       // [a][t*2+half]
__device__ float    g_invconst[NT];          // b_tr[t] - sum(W_tr[t,:])
__device__ unsigned g_pair_ctr[NB];          // per-batch block-completion counter

// monotone float<->uint encode for atomicMax on floats
__device__ __forceinline__ unsigned encf(float f) {
    unsigned u = __float_as_uint(f);
    return (u & 0x80000000u) ? ~u : (u | 0x80000000u);
}
__device__ __forceinline__ float decf(unsigned u) {
    return (u & 0x80000000u) ? __uint_as_float(u & 0x7fffffffu)
                             : __uint_as_float(~u);
}

__device__ __forceinline__ float warpdot(const float* __restrict__ a,
                                         const float* __restrict__ w, int n, int lane) {
    float s = 0.f;
    for (int d = lane; d < n; d += 32) s += a[d] * w[d];
#pragma unroll
    for (int o = 16; o; o >>= 1) s += __shfl_down_sync(0xffffffffu, s, o);
    return s;  // valid on lane 0
}

// ---------------- K1: fused pool + all dots + seg/ctr reset ----------------
// Region A (warp tasks, 8 warps/block):
#define A_OBJ  3552               // 96*37
#define A_ACT  (A_OBJ + 576)      // 96*6
#define A_IND  (A_ACT + 576)      // 96*6   inp partial dots vs W_tr
#define A_OE   (A_IND + 222)      // 37*6
#define A_AE   (A_OE + 36)        // 6*6
#define A_INV  (A_AE + 3)
#define A_WARPS A_INV             // 4965
#define A_BLOCKS ((A_WARPS + 7) / 8)   // 621
// Region B: non-exist head; one block per (b, 8-class chunk)
#define NE_CHUNKS 38              // 38*8 = 304 >= 300 classes
#define B_BLOCKS (NB * NE_CHUNKS) // 304
#define K1_BLOCKS (A_BLOCKS + B_BLOCKS)

__global__ void k_stage1(const float* __restrict__ inp,
                         const float* __restrict__ objmask,
                         const float* __restrict__ Wobj, const float* __restrict__ bobj,
                         const float* __restrict__ Wact, const float* __restrict__ bact,
                         const float* __restrict__ Wtr,  const float* __restrict__ btr,
                         const float* __restrict__ Wne,  const float* __restrict__ bne,
                         const float* __restrict__ oemb, const float* __restrict__ aemb,
                         float* __restrict__ out) {
    int tid = threadIdx.x;
    int lane = tid & 31;

    if (blockIdx.x < A_BLOCKS) {
        // ---- Region A: warp-per-dot tasks ----
        int warp = blockIdx.x * 8 + (tid >> 5);
        if (warp >= A_WARPS) return;

        if (warp < A_OBJ) {
            int c = warp % NO, bo = warp / NO;
            float r = warpdot(inp + bo * DD, Wobj + c * DD, DD, lane);
            if (lane == 0) out[OFF_OBJ + bo * NO + c] = r + bobj[c];
        } else if (warp < A_ACT) {
            int t = warp - A_OBJ;
            int c = t % NA, bo = t / NA;
            float r = warpdot(inp + bo * DD, Wact + c * DD, DD, lane);
            if (lane == 0) out[OFF_ACT + bo * NA + c] = r + bact[c];
        } else if (warp < A_IND) {
            int t = warp - A_ACT;
            int idx = t % 6, bo = t / 6;
            int tt = idx >> 1, half = idx & 1;
            float r = warpdot(inp + bo * DD, Wtr + tt * FD + half * 768, DD, lane);
            if (lane == 0) g_inpdot[bo * 6 + idx] = r;
        } else if (warp < A_OE) {
            int t = warp - A_IND;
            int idx = t % 6, o = t / 6;
            int tt = idx >> 1, half = idx & 1;
            float r = warpdot(oemb + o * EMB, Wtr + tt * FD + half * 768 + DD, EMB, lane);
            if (lane == 0) g_oembdot[o * 6 + idx] = r;
        } else if (warp < A_AE) {
            int t = warp - A_OE;
            int idx = t % 6, a = t / 6;
            int tt = idx >> 1, half = idx & 1;
            float r = warpdot(aemb + a * EMB, Wtr + tt * FD + half * 768 + DD + EMB, EMB, lane);
            if (lane == 0) g_aembdot[a * 6 + idx] = r;
        } else {
            int tt = warp - A_AE;
            float s = 0.f;
            for (int d = lane; d < FD; d += 32) s -= Wtr[tt * FD + d];
#pragma unroll
            for (int o = 16; o; o >>= 1) s += __shfl_down_sync(0xffffffffu, s, o);
            if (lane == 0) g_invconst[tt] = s + btr[tt];
        }
    } else {
        // ---- Region B: non-exist head (pooled in smem), seg clear, ctr reset ----
        int rb = blockIdx.x - A_BLOCKS;
        int b = rb / NE_CHUNKS;
        int chunk = rb % NE_CHUNKS;

        __shared__ float s_pool[DD];

        float msum = 0.f;
#pragma unroll
        for (int o = 0; o < MO; o++) msum += objmask[b * MO + o];
        float inv = 1.0f / msum;
#pragma unroll
        for (int r = 0; r < DD / 256; r++) {
            int d = tid + r * 256;
            float acc = 0.f;
#pragma unroll
            for (int o = 0; o < MO; o++)
                acc += inp[(b * MO + o) * DD + d] * objmask[b * MO + o];
            s_pool[d] = acc * inv;
        }

        if (chunk == 0) {
            for (int t = tid; t < NC; t += 256) g_seg[b * NC + t] = 0u;
            if (tid == 0) g_pair_ctr[b] = 0u;
        }
        __syncthreads();

        int c = chunk * 8 + (tid >> 5);
        if (c < NC) {
            float r = warpdot(s_pool, Wne + c * DD, DD, lane);
            if (lane == 0) g_nonexist[b * NC + c] = r + bne[c];
        }
    }
}

// ---------------- K2: pairs + fused per-batch final epilogue ----------------
__global__ void k_pairs(const float* __restrict__ out_ro,
                        const float* __restrict__ objmask,
                        const int* __restrict__ AA,
                        const float* __restrict__ TR,
                        const int* __restrict__ lookup,
                        const float* __restrict__ btr,
                        float* __restrict__ out) {
    int b = blockIdx.x;
    int tid = threadIdx.x;

    __shared__ float s_dA[KK][NT], s_dB[KK][NT];
    __shared__ int s_aa[KK];
    __shared__ unsigned s_bits[3];
    __shared__ int s_am[MO];
    __shared__ float s_btr[NT], s_inv[NT];
    __shared__ unsigned s_rank;

    if (tid < MO) {
        const float* row = out_ro + OFF_OBJ + (b * MO + tid) * NO;
        float best = row[0]; int bi = 0;
#pragma unroll
        for (int c = 1; c < NO; c++) { float v = row[c]; if (v > best) { best = v; bi = c; } }
        s_am[tid] = bi;
    }
    if (tid < NT) { s_btr[tid] = btr[tid]; s_inv[tid] = g_invconst[tid]; }
    __syncthreads();

    bool sel = false;
    if (tid < KK) {
        int o = tid / NA, a = tid % NA;
        float act = out_ro[OFF_ACT + b * KK + tid];
        float m = objmask[b * MO + o];
        float pa = (act > 0.f) ? m : 0.f;
        int aa = AA[b * KK + tid];
        sel = (pa == 1.0f) && (aa != -1);
        s_aa[tid] = aa;
        int po = s_am[o];
#pragma unroll
        for (int t = 0; t < NT; t++) {
            s_dA[tid][t] = g_inpdot[(b * MO + o) * 6 + t * 2 + 0]
                         + g_oembdot[po * 6 + t * 2 + 0]
                         + g_aembdot[a * 6 + t * 2 + 0];
            s_dB[tid][t] = g_inpdot[(b * MO + o) * 6 + t * 2 + 1]
                         + g_oembdot[po * 6 + t * 2 + 1]
                         + g_aembdot[a * 6 + t * 2 + 1];
        }
    }
    if (tid < 96) {
        unsigned bal = __ballot_sync(0xffffffffu, sel);
        if ((tid & 31) == 0) s_bits[tid >> 5] = bal;
    }
    __syncthreads();

    unsigned w0 = s_bits[0], w1 = s_bits[1], w2 = s_bits[2];
    int S = __popc(w0) + __popc(w1) + __popc(w2);
    int Nv = S * (S - 1);

    int p = blockIdx.y * blockDim.x + tid;
    if (p < NP) {
        int i = p / (KK - 1);
        int jr = p - i * (KK - 1);
        int j = jr + (jr >= i ? 1 : 0);

        auto lowmask = [](int r) -> unsigned {
            return (r >= 32) ? 0xffffffffu : ((r <= 0) ? 0u : ((1u << r) - 1u));
        };
        auto getbit = [&](int k) -> int {
            unsigned w = (k < 32) ? w0 : ((k < 64) ? w1 : w2);
            return (w >> (k & 31)) & 1;
        };
        auto pfx = [&](int k) -> int {
            return __popc(w0 & lowmask(k)) + __popc(w1 & lowmask(k - 32)) + __popc(w2 & lowmask(k - 64));
        };

        int vi = getbit(i), vj = getbit(j);
        int vb = pfx(i) * (S - 1) + (vi ? (pfx(j) - (j > i ? 1 : 0)) : 0);
        bool valid = vi && vj;
        int pos = valid ? vb : (Nv + p - vb);

        float* pl = out + OFF_PL + (size_t)(b * NP + pos) * NT;
        float* tt = out + OFF_TT + (size_t)(b * NP + pos) * NT;

        if (valid) {
            int aai = s_aa[i], aaj = s_aa[j];
            const float* tr = TR + ((size_t)(b * KK + i) * KK + j) * NT;
            const int* lk = lookup + (aai * NAA + aaj) * NT;
#pragma unroll
            for (int t = 0; t < NT; t++) {
                float lg = s_dA[i][t] + s_dB[j][t] + s_btr[t];
                pl[t] = lg;
                tt[t] = tr[t];
                atomicMax(&g_seg[b * NC + lk[t]], encf(lg));
            }
        } else {
#pragma unroll
            for (int t = 0; t < NT; t++) { pl[t] = s_inv[t]; tt[t] = -1.0f; }
        }
    }

    // ---- fused final epilogue: last block of this batch does the select ----
    __threadfence();           // make this thread's g_seg atomics device-visible
    __syncthreads();           // all threads in block have fenced
    if (tid == 0) s_rank = atomicAdd(&g_pair_ctr[b], 1u);
    __syncthreads();
    if (s_rank == gridDim.y - 1) {
        __threadfence();       // see every other block's g_seg updates
        for (int t = tid; t < NC; t += blockDim.x) {
            unsigned u = g_seg[b * NC + t];
            out[OFF_FINAL + b * NC + t] = u ? decf(u) : g_nonexist[b * NC + t];
        }
    }
}

extern "C" void kernel_launch(void* const* d_in, const int* in_sizes, int n_in,
                              void* d_out, int out_size) {
    const float* inp     = (const float*)d_in[0];
    const float* objmask = (const float*)d_in[1];
    const float* TR      = (const float*)d_in[2];
    const float* Wobj    = (const float*)d_in[3];
    const float* bobj    = (const float*)d_in[4];
    const float* Wact    = (const float*)d_in[5];
    const float* bact    = (const float*)d_in[6];
    const float* Wtr     = (const float*)d_in[7];
    const float* btr     = (const float*)d_in[8];
    const float* Wne     = (const float*)d_in[9];
    const float* bne     = (const float*)d_in[10];
    const float* oemb    = (const float*)d_in[11];
    const float* aemb    = (const float*)d_in[12];
    const int*   AA      = (const int*)d_in[13];
    // d_in[14] = obj_act_lookup (eval-only branch, unused)
    const int*   lookup  = (const int*)d_in[15];
    float* out = (float*)d_out;

    k_stage1<<<K1_BLOCKS, 256>>>(inp, objmask, Wobj, bobj, Wact, bact,
                                 Wtr, btr, Wne, bne, oemb, aemb, out);
    k_pairs<<<dim3(NB, (NP + 255) / 256), 256>>>(out, objmask, AA, TR, lookup, btr, out);
}